// round 14
// baseline (speedup 1.0000x reference)
#include <cuda_runtime.h>
#include <cuda_fp16.h>
#include <cstdint>

#define N_PROD 100000
#define N_CUST 50000
#define HID    128
#define DOUT   64
#define E_PP   800000
#define E_PC   800000
#define E_LB   400000

typedef unsigned long long u64;

#define SWZ(x) ((x) ^ (((x) >> 3) & 0x70))
#define TRIGGER_DEPENDENTS() asm volatile("griddepcontrol.launch_dependents;" ::: "memory")
#define GDC_WAIT() asm volatile("griddepcontrol.wait;" ::: "memory")

__device__ __forceinline__ uint32_t smem_u32(const void* p) {
    uint32_t a;
    asm("{ .reg .u64 t; cvta.to.shared.u64 t, %1; cvt.u32.u64 %0, t; }" : "=r"(a) : "l"(p));
    return a;
}
__device__ __forceinline__ void cp16(uint32_t dst, const void* src, int sz) {
    asm volatile("cp.async.cg.shared.global [%0],[%1],16,%2;"
                 :: "r"(dst), "l"(src), "r"(sz));
}
#define CP_COMMIT() asm volatile("cp.async.commit_group;" ::: "memory")
#define CP_WAIT1()  asm volatile("cp.async.wait_group 1;" ::: "memory")
#define CP_WAIT0()  asm volatile("cp.async.wait_group 0;" ::: "memory")

__device__ __forceinline__ void ldm4(uint32_t addr, uint32_t* r) {
    asm volatile("ldmatrix.sync.aligned.m8n8.x4.shared.b16 {%0,%1,%2,%3},[%4];"
                 : "=r"(r[0]), "=r"(r[1]), "=r"(r[2]), "=r"(r[3]) : "r"(addr));
}
__device__ __forceinline__ void mma_f16(float* d, const uint32_t* a,
                                        uint32_t b0, uint32_t b1) {
    asm volatile(
        "mma.sync.aligned.m16n8k16.row.col.f32.f16.f16.f32 "
        "{%0,%1,%2,%3},{%4,%5,%6,%7},{%8,%9},{%0,%1,%2,%3};"
        : "+f"(d[0]), "+f"(d[1]), "+f"(d[2]), "+f"(d[3])
        : "r"(a[0]), "r"(a[1]), "r"(a[2]), "r"(a[3]), "r"(b0), "r"(b1));
}
__device__ __forceinline__ void split1h(float w, unsigned short& h, unsigned short& l) {
    __half hh = __float2half_rn(w);
    __half hl = __float2half_rn(w - __half2float(hh));
    h = __half_as_ushort(hh);
    l = __half_as_ushort(hl);
}
__device__ __forceinline__ u64 pack4h(float a0, float a1, float a2, float a3) {
    __half2 p0 = __floats2half2_rn(a0, a1);
    __half2 p1 = __floats2half2_rn(a2, a3);
    u64 r;
    asm("mov.b64 %0,{%1,%2};" : "=l"(r)
        : "r"(*reinterpret_cast<uint32_t*>(&p0)), "r"(*reinterpret_cast<uint32_t*>(&p1)));
    return r;
}

// ---------------------------------------------------------------------------
// Scratch
// ---------------------------------------------------------------------------
__device__ __half g_xP[(size_t)N_PROD * HID];
__device__ __half g_xC[(size_t)N_CUST * HID];
__device__ __half g_M0[(size_t)N_PROD * HID];
__device__ __half g_M0C[(size_t)N_CUST * HID];
__device__ __half g_P1[(size_t)N_PROD * HID];
__device__ __half g_P2[(size_t)N_PROD * HID];
__device__ __half g_C1[(size_t)N_CUST * HID];
__device__ __half g_zprod[(size_t)N_PROD * DOUT];
__device__ __half g_zcust[(size_t)N_CUST * DOUT];

__device__ int g_cntP[N_PROD];
__device__ int g_cntC[N_CUST];
__device__ int g_offP[N_PROD];
__device__ int g_csrP[E_PP];
__device__ int g_offC[N_CUST];
__device__ int g_csrC[E_PC];
__device__ int g_rankP[E_PP];
__device__ int g_rankC[E_PC];
__device__ u64 g_lbP[128];
__device__ u64 g_lbC[64];

// ---------------------------------------------------------------------------
// Launch 0: convert x -> fp16 planes (independent of CSR chain)
// ---------------------------------------------------------------------------
__global__ void k_convert(const float* __restrict__ xp, const float* __restrict__ xc) {
    if (blockIdx.x == 0 && threadIdx.x == 0) TRIGGER_DEPENDENTS();
    const int NP4 = N_PROD * HID / 4;
    const int NC4 = N_CUST * HID / 4;
    int i = blockIdx.x * blockDim.x + threadIdx.x;
    if (i >= NP4 + NC4) return;
    const float* src; __half* dh; int o;
    if (i < NP4) { src = xp; dh = g_xP; o = i; }
    else { src = xc; dh = g_xC; o = i - NP4; }
    float4 v = *reinterpret_cast<const float4*>(src + (size_t)o * 4);
    *reinterpret_cast<u64*>(dh + (size_t)o * 4) = pack4h(v.x, v.y, v.z, v.w);
}

// Launch 1 [PDL]: count both edge histograms, recording each edge's rank
__global__ void k_count2x(const int* __restrict__ dstP, const int* __restrict__ dstC) {
    int j = blockIdx.x * blockDim.x + threadIdx.x;
    if (j < E_PP) { g_rankP[j] = atomicAdd(&g_cntP[dstP[j]], 1); return; }
    j -= E_PP;
    if (j < E_PC) g_rankC[j] = atomicAdd(&g_cntC[dstC[j]], 1);
}

// ---------------------------------------------------------------------------
// Launch 2 [PDL+wait]: decoupled-lookback scan (P and C segments)
// ---------------------------------------------------------------------------
__device__ void scan_seg(const int* __restrict__ cnt, int n,
                         int* __restrict__ off, u64* __restrict__ st, int bid) {
    __shared__ int s[1024];
    __shared__ int s_prefix;
    int tx = threadIdx.x;
    int gid = bid * 1024 + tx;
    int v = (gid < n) ? cnt[gid] : 0;
    s[tx] = v;
    __syncthreads();
#pragma unroll
    for (int d = 1; d < 1024; d <<= 1) {
        int t = (tx >= d) ? s[tx - d] : 0;
        __syncthreads();
        s[tx] += t;
        __syncthreads();
    }
    int incl = s[tx];
    int total = s[1023];
    if (tx == 0) {
        if (bid == 0) {
            s_prefix = 0;
            atomicExch(st, ((u64)(unsigned)total << 32) | 2ULL);
        } else {
            atomicExch(st + bid, ((u64)(unsigned)total << 32) | 1ULL);
            int run = 0, j = bid - 1;
            while (true) {
                u64 x;
                do { x = atomicAdd(st + j, 0ULL); } while ((x & 3ULL) == 0ULL);
                run += (int)(unsigned)(x >> 32);
                if ((x & 3ULL) == 2ULL) break;
                j--;
            }
            s_prefix = run;
            atomicExch(st + bid, ((u64)(unsigned)(run + total) << 32) | 2ULL);
        }
    }
    __syncthreads();
    if (gid < n) off[gid] = s_prefix + incl - v;
}

__global__ void k_scan2x() {
    GDC_WAIT();
    const int nbP = (N_PROD + 1023) / 1024;
    if ((int)blockIdx.x < nbP)
        scan_seg(g_cntP, N_PROD, g_offP, g_lbP, blockIdx.x);
    else
        scan_seg(g_cntC, N_CUST, g_offC, g_lbC, blockIdx.x - nbP);
}

// Launch 3 [PDL+wait]: atomic-free fill using recorded ranks
__global__ void k_fill2x(const int* __restrict__ eP, const int* __restrict__ eC) {
    GDC_WAIT();
    int e = blockIdx.x * blockDim.x + threadIdx.x;
    if (e < E_PP) {
        int d = eP[E_PP + e];
        g_csrP[g_offP[d] + g_rankP[e]] = eP[e];
    } else if (e < E_PP + E_PC) {
        int j = e - E_PP;
        int d = eC[E_PC + j];
        g_csrC[g_offC[d] + g_rankC[j]] = eC[j];
    }
}

// ---------------------------------------------------------------------------
// Mean aggregation body: 16 lanes per row via LDG.128, even/odd edge split
// ---------------------------------------------------------------------------
__device__ __forceinline__ void agg_body(const __half* __restrict__ x,
                                         const int* __restrict__ off,
                                         const int* __restrict__ csr,
                                         __half* __restrict__ o,
                                         int w, int n, int E, int lane) {
    int beg = off[w];
    int end = (w + 1 < n) ? off[w + 1] : E;
    const int half = lane >> 4, sub = lane & 15;
    float a[8];
#pragma unroll
    for (int q = 0; q < 8; q++) a[q] = 0.f;

#define ACC16(v) do { \
    float2 f0 = __half22float2(*reinterpret_cast<__half2*>(&(v).x)); \
    float2 f1 = __half22float2(*reinterpret_cast<__half2*>(&(v).y)); \
    float2 f2 = __half22float2(*reinterpret_cast<__half2*>(&(v).z)); \
    float2 f3 = __half22float2(*reinterpret_cast<__half2*>(&(v).w)); \
    a[0] += f0.x; a[1] += f0.y; a[2] += f1.x; a[3] += f1.y; \
    a[4] += f2.x; a[5] += f2.y; a[6] += f3.x; a[7] += f3.y; \
} while (0)

    int j = beg + half;
    for (; j + 2 < end; j += 4) {
        int s0 = csr[j], s1 = csr[j + 2];
        uint4 v0 = __ldg(reinterpret_cast<const uint4*>(x + (size_t)s0 * HID + sub * 8));
        uint4 v1 = __ldg(reinterpret_cast<const uint4*>(x + (size_t)s1 * HID + sub * 8));
        ACC16(v0); ACC16(v1);
    }
    if (j < end) {
        int s0 = csr[j];
        uint4 v0 = __ldg(reinterpret_cast<const uint4*>(x + (size_t)s0 * HID + sub * 8));
        ACC16(v0);
    }
#undef ACC16

#pragma unroll
    for (int q = 0; q < 8; q++)
        a[q] += __shfl_xor_sync(0xffffffff, a[q], 16);

    if (half == 0) {
        float sc = (end > beg) ? 1.0f / (float)(end - beg) : 0.f;
        __half2 h0 = __floats2half2_rn(a[0] * sc, a[1] * sc);
        __half2 h1 = __floats2half2_rn(a[2] * sc, a[3] * sc);
        __half2 h2 = __floats2half2_rn(a[4] * sc, a[5] * sc);
        __half2 h3 = __floats2half2_rn(a[6] * sc, a[7] * sc);
        uint4 u;
        u.x = *reinterpret_cast<uint32_t*>(&h0);
        u.y = *reinterpret_cast<uint32_t*>(&h1);
        u.z = *reinterpret_cast<uint32_t*>(&h2);
        u.w = *reinterpret_cast<uint32_t*>(&h3);
        *reinterpret_cast<uint4*>(o + (size_t)w * HID + sub * 8) = u;
    }
}

// Both x-aggregations in one launch
__global__ void agg2x() {
    int w = (blockIdx.x * blockDim.x + threadIdx.x) >> 5;
    int lane = threadIdx.x & 31;
    if (w < N_PROD)
        agg_body(g_xP, g_offP, g_csrP, g_M0, w, N_PROD, E_PP, lane);
    else if (w < N_PROD + N_CUST)
        agg_body(g_xP, g_offC, g_csrC, g_M0C, w - N_PROD, N_CUST, E_PC, lane);
}

// Both layer-2 aggregations in one launch
__global__ void agg2b() {
    int w = (blockIdx.x * blockDim.x + threadIdx.x) >> 5;
    int lane = threadIdx.x & 31;
    if (w < N_PROD)
        agg_body(g_P1, g_offP, g_csrP, g_M0, w, N_PROD, E_PP, lane);
    else if (w < N_PROD + N_CUST)
        agg_body(g_P2, g_offC, g_csrC, g_M0C, w - N_PROD, N_CUST, E_PC, lane);
}

// ---------------------------------------------------------------------------
// Dual f16 GEMM (2-term weight split), K=256, N=128, MTILE=256, relu.
//   FUSE2: restage relu'd tile and run second GEMM (128->64), write fp16 z.
// ---------------------------------------------------------------------------
template <bool FUSE2>
__global__ __launch_bounds__(512, 1) void hmma_dual(
    const __half* __restrict__ A, const __half* __restrict__ X,
    const float* __restrict__ Wl, const float* __restrict__ Wr,
    const float* __restrict__ bias,
    const float* __restrict__ W2, const float* __restrict__ b2,
    __half* __restrict__ outP, __half* __restrict__ out2,
    int n, int trig)
{
    if (trig) TRIGGER_DEPENDENTS();
    constexpr int KSTEPS = 16;
    constexpr int NF2    = 8;
    constexpr int MTILE  = 256;
    constexpr int CHUNKB = MTILE * 128;
    constexpr int BOFF   = 1024 + 2 * CHUNKB;
    constexpr int BSPLIT = KSTEPS * NF2 * 32 * 16;
    constexpr int BOFF2  = BOFF + 2 * BSPLIT;
    constexpr int BSPLIT2 = 8 * 4 * 32 * 16;
    constexpr int NCHUNK = 4;
    constexpr int CPOPS  = MTILE * 8;

    extern __shared__ char smem[];
    const uint32_t sb = smem_u32(smem);
    const int tid = threadIdx.x;
    const int w = tid >> 5, lane = tid & 31;
    const int g     = w & 1;
    const int warpM = (w >> 1) * 32;

    float* bs = (float*)smem;
    float* bs2 = (float*)(smem + 512);
    if (tid < 128) bs[tid] = bias[tid];
    if (FUSE2 && tid >= 128 && tid < 192) bs2[tid - 128] = b2[tid - 128];

    for (int idx = tid; idx < 2 * KSTEPS * NF2 * 32; idx += 512) {
        int l = idx & 31;
        int rest = idx >> 5;
        int nfp = rest % NF2;
        int rest2 = rest / NF2;
        int ks = rest2 % KSTEPS;
        int s = rest2 / KSTEPS;
        uint32_t vals[4];
#pragma unroll
        for (int e = 0; e < 2; e++) {
            int nf = nfp * 2 + e;
            int nn = nf * 8 + (l >> 2);
            int k0 = ks * 16 + (l & 3) * 2;
            const float* wp = Wl;
            int kk = k0;
            if (k0 >= 128) { wp = Wr; kk = k0 - 128; }
            float2 wa = *reinterpret_cast<const float2*>(wp + nn * 128 + kk);
            float2 wb = *reinterpret_cast<const float2*>(wp + nn * 128 + kk + 8);
            unsigned short h, lo, r00, r01, r10, r11;
            split1h(wa.x, h, lo); r00 = s ? lo : h;
            split1h(wa.y, h, lo); r01 = s ? lo : h;
            split1h(wb.x, h, lo); r10 = s ? lo : h;
            split1h(wb.y, h, lo); r11 = s ? lo : h;
            vals[e * 2 + 0] = (uint32_t)r00 | ((uint32_t)r01 << 16);
            vals[e * 2 + 1] = (uint32_t)r10 | ((uint32_t)r11 << 16);
        }
        *reinterpret_cast<uint4*>(smem + BOFF + (size_t)idx * 16) =
            make_uint4(vals[0], vals[1], vals[2], vals[3]);
    }
    if (FUSE2) {
        for (int idx = tid; idx < 2 * 8 * 4 * 32; idx += 512) {
            int l = idx & 31;
            int rest = idx >> 5;
            int nfp = rest % 4;
            int rest2 = rest / 4;
            int ks = rest2 % 8;
            int s = rest2 / 8;
            uint32_t vals[4];
#pragma unroll
            for (int e = 0; e < 2; e++) {
                int nf = nfp * 2 + e;
                int nn = nf * 8 + (l >> 2);
                int k0 = ks * 16 + (l & 3) * 2;
                float2 wa = *reinterpret_cast<const float2*>(W2 + nn * 128 + k0);
                float2 wb = *reinterpret_cast<const float2*>(W2 + nn * 128 + k0 + 8);
                unsigned short h, lo, r00, r01, r10, r11;
                split1h(wa.x, h, lo); r00 = s ? lo : h;
                split1h(wa.y, h, lo); r01 = s ? lo : h;
                split1h(wb.x, h, lo); r10 = s ? lo : h;
                split1h(wb.y, h, lo); r11 = s ? lo : h;
                vals[e * 2 + 0] = (uint32_t)r00 | ((uint32_t)r01 << 16);
                vals[e * 2 + 1] = (uint32_t)r10 | ((uint32_t)r11 << 16);
            }
            *reinterpret_cast<uint4*>(smem + BOFF2 + (size_t)idx * 16) =
                make_uint4(vals[0], vals[1], vals[2], vals[3]);
        }
    }
    __syncthreads();

    const int ntiles = (n + MTILE - 1) / MTILE;

    for (int tt = blockIdx.x; tt < ntiles; tt += gridDim.x) {
        float acc[2][8][4];
#pragma unroll
        for (int t = 0; t < 2; t++)
#pragma unroll
            for (int nf = 0; nf < 8; nf++)
#pragma unroll
                for (int q = 0; q < 4; q++) acc[t][nf][q] = 0.f;

        auto stage = [&](int c, int b) {
            const __half* src = (c >= 2) ? X : A;
            const int colbase = (c & 1) * 64;
#pragma unroll
            for (int it = 0; it < CPOPS / 512; it++) {
                int u = tid + it * 512;
                int r0 = u >> 3;
                int ch = u & 7;
                int gr = tt * MTILE + r0;
                uint32_t dst = sb + 1024 + b * CHUNKB +
                               SWZ((uint32_t)(r0 * 128 + ch * 16));
                const void* gp = src + (size_t)gr * 128 + colbase + ch * 8;
                cp16(dst, gp, (gr < n) ? 16 : 0);
            }
            CP_COMMIT();
        };

        stage(0, 0);

        for (int c = 0; c < NCHUNK; c++) {
            if (c + 1 < NCHUNK) { stage(c + 1, (c + 1) & 1); CP_WAIT1(); }
            else CP_WAIT0();
            __syncthreads();

            const uint32_t abase = sb + 1024 + (c & 1) * CHUNKB;
#pragma unroll
            for (int ksl = 0; ksl < 4; ksl++) {
                const int ks = c * 4 + ksl;
                uint32_t ah[2][4];
#pragma unroll
                for (int t = 0; t < 2; t++) {
                    int arow = warpM + t * 16 + (lane & 15);
                    int colb = ksl * 32 + ((lane >> 4) << 4);
                    ldm4(abase + SWZ((uint32_t)(arow * 128 + colb)), ah[t]);
                }
                uint4 Bq[4];
                {
                    size_t base = (size_t)BOFF +
                        ((size_t)(ks * NF2 + g * 4) * 32 + lane) * 16;
#pragma unroll
                    for (int p = 0; p < 4; p++)
                        Bq[p] = *reinterpret_cast<const uint4*>(smem + base + p * 512);
                }
#pragma unroll
                for (int t = 0; t < 2; t++)
#pragma unroll
                    for (int nf = 0; nf < 8; nf++) {
                        uint32_t b0 = (nf & 1) ? Bq[nf >> 1].z : Bq[nf >> 1].x;
                        uint32_t b1 = (nf & 1) ? Bq[nf >> 1].w : Bq[nf >> 1].y;
                        mma_f16(acc[t][nf], ah[t], b0, b1);
                    }
                {
                    size_t base = (size_t)BOFF + BSPLIT +
                        ((size_t)(ks * NF2 + g * 4) * 32 + lane) * 16;
#pragma unroll
                    for (int p = 0; p < 4; p++)
                        Bq[p] = *reinterpret_cast<const uint4*>(smem + base + p * 512);
                }
#pragma unroll
                for (int t = 0; t < 2; t++)
#pragma unroll
                    for (int nf = 0; nf < 8; nf++) {
                        uint32_t b0 = (nf & 1) ? Bq[nf >> 1].z : Bq[nf >> 1].x;
                        uint32_t b1 = (nf & 1) ? Bq[nf >> 1].w : Bq[nf >> 1].y;
                        mma_f16(acc[t][nf], ah[t], b0, b1);
                    }
            }
            __syncthreads();
        }

        if (!FUSE2) {
#pragma unroll
            for (int t = 0; t < 2; t++) {
                int rbase = tt * MTILE + warpM + t * 16 + (lane >> 2);
#pragma unroll
                for (int nf = 0; nf < 8; nf++) {
                    int col = g * 64 + nf * 8 + (lane & 3) * 2;
#pragma unroll
                    for (int hh = 0; hh < 2; hh++) {
                        int row = rbase + hh * 8;
                        if (row < n) {
                            float ox = fmaxf(acc[t][nf][hh * 2 + 0] + bs[col], 0.f);
                            float oy = fmaxf(acc[t][nf][hh * 2 + 1] + bs[col + 1], 0.f);
                            __half2 hp = __floats2half2_rn(ox, oy);
                            *reinterpret_cast<uint32_t*>(outP + (size_t)row * 128 + col) =
                                *reinterpret_cast<uint32_t*>(&hp);
                        }
                    }
                }
            }
        } else {
#pragma unroll
            for (int t = 0; t < 2; t++) {
                int rl = warpM + t * 16 + (lane >> 2);
#pragma unroll
                for (int nf = 0; nf < 8; nf++) {
                    int col = g * 64 + nf * 8 + (lane & 3) * 2;
#pragma unroll
                    for (int hh = 0; hh < 2; hh++) {
                        int r = rl + hh * 8;
                        float ox = fmaxf(acc[t][nf][hh * 2 + 0] + bs[col], 0.f);
                        float oy = fmaxf(acc[t][nf][hh * 2 + 1] + bs[col + 1], 0.f);
                        __half2 hp = __floats2half2_rn(ox, oy);
                        uint32_t off = SWZ((uint32_t)(r * 128 + (col & 63) * 2));
                        *reinterpret_cast<uint32_t*>(smem + 1024 + g * CHUNKB + off) =
                            *reinterpret_cast<uint32_t*>(&hp);
                    }
                }
            }
            __syncthreads();

            float acc2[2][4][4];
#pragma unroll
            for (int t = 0; t < 2; t++)
#pragma unroll
                for (int nf = 0; nf < 4; nf++)
#pragma unroll
                    for (int q = 0; q < 4; q++) acc2[t][nf][q] = 0.f;

#pragma unroll
            for (int ks2 = 0; ks2 < 8; ks2++) {
                const int chunk = ks2 >> 2, ksl2 = ks2 & 3;
                const uint32_t abase2 = sb + 1024 + chunk * CHUNKB;
                uint32_t ah2[2][4];
#pragma unroll
                for (int t = 0; t < 2; t++) {
                    int arow = warpM + t * 16 + (lane & 15);
                    int colb = ksl2 * 32 + ((lane >> 4) << 4);
                    ldm4(abase2 + SWZ((uint32_t)(arow * 128 + colb)), ah2[t]);
                }
                uint4 Bq[2];
                {
                    size_t base = (size_t)BOFF2 +
                        ((size_t)(ks2 * 4 + g * 2) * 32 + lane) * 16;
                    Bq[0] = *reinterpret_cast<const uint4*>(smem + base);
                    Bq[1] = *reinterpret_cast<const uint4*>(smem + base + 512);
                }
#pragma unroll
                for (int t = 0; t < 2; t++)
#pragma unroll
                    for (int nf = 0; nf < 4; nf++) {
                        uint32_t b0 = (nf & 1) ? Bq[nf >> 1].z : Bq[nf >> 1].x;
                        uint32_t b1 = (nf & 1) ? Bq[nf >> 1].w : Bq[nf >> 1].y;
                        mma_f16(acc2[t][nf], ah2[t], b0, b1);
                    }
                {
                    size_t base = (size_t)BOFF2 + BSPLIT2 +
                        ((size_t)(ks2 * 4 + g * 2) * 32 + lane) * 16;
                    Bq[0] = *reinterpret_cast<const uint4*>(smem + base);
                    Bq[1] = *reinterpret_cast<const uint4*>(smem + base + 512);
                }
#pragma unroll
                for (int t = 0; t < 2; t++)
#pragma unroll
                    for (int nf = 0; nf < 4; nf++) {
                        uint32_t b0 = (nf & 1) ? Bq[nf >> 1].z : Bq[nf >> 1].x;
                        uint32_t b1 = (nf & 1) ? Bq[nf >> 1].w : Bq[nf >> 1].y;
                        mma_f16(acc2[t][nf], ah2[t], b0, b1);
                    }
            }

#pragma unroll
            for (int t = 0; t < 2; t++) {
                int rbase = tt * MTILE + warpM + t * 16 + (lane >> 2);
#pragma unroll
                for (int nf = 0; nf < 4; nf++) {
                    int col = g * 32 + nf * 8 + (lane & 3) * 2;
#pragma unroll
                    for (int hh = 0; hh < 2; hh++) {
                        int row = rbase + hh * 8;
                        if (row < n) {
                            __half2 hp = __floats2half2_rn(
                                acc2[t][nf][hh * 2 + 0] + bs2[col],
                                acc2[t][nf][hh * 2 + 1] + bs2[col + 1]);
                            *reinterpret_cast<uint32_t*>(out2 + (size_t)row * 64 + col) =
                                *reinterpret_cast<uint32_t*>(&hp);
                        }
                    }
                }
            }
            __syncthreads();
        }
    }
}

// ---------------------------------------------------------------------------
// HMMA decoder (+ scratch zeroing prologue)
// ---------------------------------------------------------------------------
__global__ __launch_bounds__(512, 1) void decoder_hmma(
    const __half* __restrict__ zc, const __half* __restrict__ zp,
    const int* __restrict__ rowIdx, const int* __restrict__ colIdx,
    const float* __restrict__ W1, const float* __restrict__ b1,
    const float* __restrict__ w2, const float* __restrict__ b2,
    float* __restrict__ out, int nE)
{
    constexpr int MTILE  = 256;
    constexpr int CHUNKB = MTILE * 128;
    constexpr int BOFF   = 1024 + 2 * CHUNKB;
    constexpr int BSPLIT = 8 * 4 * 32 * 16;

    for (int i = blockIdx.x * blockDim.x + threadIdx.x; i < N_PROD;
         i += gridDim.x * blockDim.x) {
        g_cntP[i] = 0;
        if (i < N_CUST) g_cntC[i] = 0;
        if (i < 128) g_lbP[i] = 0;
        if (i < 64) g_lbC[i] = 0;
    }

    extern __shared__ char smem[];
    const uint32_t sb = smem_u32(smem);
    const int tid = threadIdx.x;
    const int w = tid >> 5, lane = tid & 31;
    const int warpM = w * 16;

    float* ps = (float*)smem;
    if (tid < 64) ps[tid] = b1[tid];
    else if (tid < 128) ps[tid] = w2[tid - 64];
    else if (tid == 128) ps[128] = b2[0];

    for (int idx = tid; idx < 2 * 8 * 4 * 32; idx += 512) {
        int l = idx & 31;
        int rest = idx >> 5;
        int nfp = rest % 4;
        int rest2 = rest / 4;
        int ks = rest2 % 8;
        int s = rest2 / 8;
        uint32_t vals[4];
#pragma unroll
        for (int e = 0; e < 2; e++) {
            int nf = nfp * 2 + e;
            int nn = nf * 8 + (l >> 2);
            int k0 = ks * 16 + (l & 3) * 2;
            float2 wa = *reinterpret_cast<const float2*>(W1 + nn * 128 + k0);
            float2 wb = *reinterpret_cast<const float2*>(W1 + nn * 128 + k0 + 8);
            unsigned short h, lo, r00, r01, r10, r11;
            split1h(wa.x, h, lo); r00 = s ? lo : h;
            split1h(wa.y, h, lo); r01 = s ? lo : h;
            split1h(wb.x, h, lo); r10 = s ? lo : h;
            split1h(wb.y, h, lo); r11 = s ? lo : h;
            vals[e * 2 + 0] = (uint32_t)r00 | ((uint32_t)r01 << 16);
            vals[e * 2 + 1] = (uint32_t)r10 | ((uint32_t)r11 << 16);
        }
        *reinterpret_cast<uint4*>(smem + BOFF + (size_t)idx * 16) =
            make_uint4(vals[0], vals[1], vals[2], vals[3]);
    }
    __syncthreads();

    const int ntiles = (nE + MTILE - 1) / MTILE;

    for (int tt = blockIdx.x; tt < ntiles; tt += gridDim.x) {
        float acc[8][4];
#pragma unroll
        for (int nf = 0; nf < 8; nf++)
#pragma unroll
            for (int q = 0; q < 4; q++) acc[nf][q] = 0.f;

        auto stage = [&](int c, int b) {
            const __half* src = (c == 0) ? zc : zp;
            const int* idxp = (c == 0) ? rowIdx : colIdx;
#pragma unroll
            for (int it = 0; it < 4; it++) {
                int u = tid + it * 512;
                int r0 = u >> 3;
                int ch = u & 7;
                int e = tt * MTILE + r0;
                int idx = (e < nE) ? __ldg(idxp + e) : -1;
                uint32_t dst = sb + 1024 + b * CHUNKB +
                               SWZ((uint32_t)(r0 * 128 + ch * 16));
                const void* gp = src + (size_t)(idx < 0 ? 0 : idx) * 64 + ch * 8;
                cp16(dst, gp, (idx >= 0) ? 16 : 0);
            }
            CP_COMMIT();
        };

        stage(0, 0);

        for (int c = 0; c < 2; c++) {
            if (c == 0) { stage(1, 1); CP_WAIT1(); }
            else CP_WAIT0();
            __syncthreads();

            const uint32_t abase = sb + 1024 + c * CHUNKB;
#pragma unroll
            for (int ksl = 0; ksl < 4; ksl++) {
                const int ks = c * 4 + ksl;
                uint32_t ah[4];
                {
                    int arow = warpM + (lane & 15);
                    int colb = ksl * 32 + ((lane >> 4) << 4);
                    ldm4(abase + SWZ((uint32_t)(arow * 128 + colb)), ah);
                }
                uint4 Bq[4];
                {
                    size_t base = (size_t)BOFF + ((size_t)(ks * 4) * 32 + lane) * 16;
#pragma unroll
                    for (int p = 0; p < 4; p++)
                        Bq[p] = *reinterpret_cast<const uint4*>(smem + base + p * 512);
                }
#pragma unroll
                for (int nf = 0; nf < 8; nf++) {
                    uint32_t b0 = (nf & 1) ? Bq[nf >> 1].z : Bq[nf >> 1].x;
                    uint32_t b1v = (nf & 1) ? Bq[nf >> 1].w : Bq[nf >> 1].y;
                    mma_f16(acc[nf], ah, b0, b1v);
                }
                {
                    size_t base = (size_t)BOFF + BSPLIT + ((size_t)(ks * 4) * 32 + lane) * 16;
#pragma unroll
                    for (int p = 0; p < 4; p++)
                        Bq[p] = *reinterpret_cast<const uint4*>(smem + base + p * 512);
                }
#pragma unroll
                for (int nf = 0; nf < 8; nf++) {
                    uint32_t b0 = (nf & 1) ? Bq[nf >> 1].z : Bq[nf >> 1].x;
                    uint32_t b1v = (nf & 1) ? Bq[nf >> 1].w : Bq[nf >> 1].y;
                    mma_f16(acc[nf], ah, b0, b1v);
                }
            }
            __syncthreads();
        }

        {
            float p0 = 0.f, p1 = 0.f;
#pragma unroll
            for (int nf = 0; nf < 8; nf++) {
                int col = nf * 8 + (lane & 3) * 2;
                float w20 = ps[64 + col], w21 = ps[64 + col + 1];
                float bb0 = ps[col], bb1 = ps[col + 1];
                p0 += fmaxf(acc[nf][0] + bb0, 0.f) * w20 +
                      fmaxf(acc[nf][1] + bb1, 0.f) * w21;
                p1 += fmaxf(acc[nf][2] + bb0, 0.f) * w20 +
                      fmaxf(acc[nf][3] + bb1, 0.f) * w21;
            }
            p0 += __shfl_xor_sync(0xffffffff, p0, 1);
            p0 += __shfl_xor_sync(0xffffffff, p0, 2);
            p1 += __shfl_xor_sync(0xffffffff, p1, 1);
            p1 += __shfl_xor_sync(0xffffffff, p1, 2);
            if ((lane & 3) == 0) {
                int e0 = tt * MTILE + warpM + (lane >> 2);
                if (e0 < nE) out[e0] = p0 + ps[128];
                if (e0 + 8 < nE) out[e0 + 8] = p1 + ps[128];
            }
        }
    }
}

// ---------------------------------------------------------------------------
// Host orchestration
// ---------------------------------------------------------------------------
extern "C" void kernel_launch(void* const* d_in, const int* in_sizes, int n_in,
                              void* d_out, int out_size) {
    const float* x_prod = (const float*)d_in[0];
    const float* x_cust = (const float*)d_in[1];
    const int* pp = (const int*)d_in[2];
    const int* pc = (const int*)d_in[3];
    const int* eli = (const int*)d_in[4];

    bool sig = (in_sizes[6] == HID);
    const float* it_W1l = (const float*)d_in[5];
    const float* it_W1r = (const float*)d_in[sig ? 7 : 6];
    const float* it_b1  = (const float*)d_in[sig ? 6 : 7];
    const float* it_W2l = (const float*)d_in[8];
    const float* it_W2r = (const float*)d_in[sig ? 10 : 9];
    const float* it_b2  = (const float*)d_in[sig ? 9 : 10];
    const float* it_Wlin = (const float*)d_in[11];
    const float* it_blin = (const float*)d_in[12];
    const float* us_W1l = (const float*)d_in[13];
    const float* us_W1r = (const float*)d_in[sig ? 15 : 14];
    const float* us_b1  = (const float*)d_in[sig ? 14 : 15];
    const float* us_W2l = (const float*)d_in[16];
    const float* us_W2r = (const float*)d_in[sig ? 18 : 17];
    const float* us_b2  = (const float*)d_in[sig ? 17 : 18];
    const float* us_W3l = (const float*)d_in[19];
    const float* us_W3r = (const float*)d_in[sig ? 21 : 20];
    const float* us_b3  = (const float*)d_in[sig ? 20 : 21];
    const float* us_Wlin = (const float*)d_in[22];
    const float* us_blin = (const float*)d_in[23];
    const float* de_W1 = (const float*)d_in[24];
    const float* de_b1 = (const float*)d_in[25];
    const float* de_W2 = (const float*)d_in[26];
    const float* de_b2 = (const float*)d_in[27];

#define GETP(var, sym, T) T* var; cudaGetSymbolAddress((void**)&var, sym)
    GETP(xP, g_xP, __half); GETP(xC, g_xC, __half);
    GETP(M0, g_M0, __half); GETP(M0C, g_M0C, __half);
    GETP(P1, g_P1, __half); GETP(P2, g_P2, __half);
    GETP(C1, g_C1, __half);
    GETP(zprod, g_zprod, __half); GETP(zcust, g_zcust, __half);
    GETP(offP, g_offP, int); GETP(csrP, g_csrP, int);
    GETP(offC, g_offC, int); GETP(csrC, g_csrC, int);
#undef GETP

    constexpr int SM_PLAIN = 1024 + 2 * 32768 + 2 * 65536;   // 197632
    constexpr int SM_FUSED = SM_PLAIN + 2 * 16384;           // 230400
    constexpr int SM_DEC   = 1024 + 2 * 32768 + 2 * 16384;   // 99328
    cudaFuncSetAttribute((hmma_dual<false>),
                         cudaFuncAttributeMaxDynamicSharedMemorySize, SM_PLAIN);
    cudaFuncSetAttribute((hmma_dual<true>),
                         cudaFuncAttributeMaxDynamicSharedMemorySize, SM_FUSED);
    cudaFuncSetAttribute(decoder_hmma,
                         cudaFuncAttributeMaxDynamicSharedMemorySize, SM_DEC);

    const int nbP = (N_PROD + 1023) / 1024;
    const int nbC = (N_CUST + 1023) / 1024;
    const int CVT_ITEMS = (N_PROD + N_CUST) * HID / 4;
    const int agg2x_grid = ((N_PROD + N_CUST) * 32 + 255) / 256;

    cudaLaunchAttribute pdlAttr[1];
    pdlAttr[0].id = cudaLaunchAttributeProgrammaticStreamSerialization;
    pdlAttr[0].val.programmaticStreamSerializationAllowed = 1;

    auto mkCfg = [&](int grid, int block, int smem) {
        cudaLaunchConfig_t c{};
        c.gridDim = dim3(grid); c.blockDim = dim3(block);
        c.dynamicSmemBytes = smem; c.stream = 0;
        c.attrs = pdlAttr; c.numAttrs = 1;
        return c;
    };

    // 0: convert (triggers immediately so CSR chain overlaps)
    k_convert<<<(CVT_ITEMS + 255) / 256, 256>>>(x_prod, x_cust);
    // 1: counts + ranks [PDL]
    {
        cudaLaunchConfig_t c = mkCfg((E_PP + E_PC + 255) / 256, 256, 0);
        cudaLaunchKernelEx(&c, k_count2x, (const int*)(pp + E_PP), (const int*)(pc + E_PC));
    }
    // 2: scan [PDL + gdc.wait]
    {
        cudaLaunchConfig_t c = mkCfg(nbP + nbC, 1024, 0);
        cudaLaunchKernelEx(&c, k_scan2x);
    }
    // 3: atomic-free fill [PDL + gdc.wait]
    {
        cudaLaunchConfig_t c = mkCfg((E_PP + E_PC + 255) / 256, 256, 0);
        cudaLaunchKernelEx(&c, k_fill2x, (const int*)pp, (const int*)pc);
    }

    // 4: both x-aggregations
    agg2x<<<agg2x_grid, 256>>>();

    // 5-7: G1, G2, G5 mutually independent
    hmma_dual<false><<<148, 512, SM_PLAIN>>>(
        M0, xP, it_W1l, it_W1r, it_b1, nullptr, nullptr, P1, nullptr, N_PROD, 1);
    {
        cudaLaunchConfig_t c = mkCfg(148, 512, SM_PLAIN);
        cudaLaunchKernelEx(&c, hmma_dual<false>,
            (const __half*)M0, (const __half*)xP, us_W1l, us_W1r, us_b1,
            (const float*)nullptr, (const float*)nullptr,
            (__half*)P2, (__half*)nullptr, (int)N_PROD, 1);
        cudaLaunchKernelEx(&c, hmma_dual<false>,
            (const __half*)M0C, (const __half*)xC, us_W2l, us_W2r, us_b2,
            (const float*)nullptr, (const float*)nullptr,
            (__half*)C1, (__half*)nullptr, (int)N_CUST, 0);
    }

    // 8: merged layer-2 aggregations
    agg2b<<<agg2x_grid, 256>>>();

    // 9-10: fused G3 ‖ fused G6
    hmma_dual<true><<<148, 512, SM_FUSED>>>(
        M0, P1, it_W2l, it_W2r, it_b2, it_Wlin, it_blin, nullptr, zprod, N_PROD, 1);
    {
        cudaLaunchConfig_t c = mkCfg(148, 512, SM_FUSED);
        cudaLaunchKernelEx(&c, hmma_dual<true>,
            (const __half*)M0C, (const __half*)C1, us_W3l, us_W3r, us_b3,
            us_Wlin, us_blin, (__half*)nullptr, (__half*)zcust, (int)N_CUST, 0);
    }

    // 11: HMMA decoder (+ zero-invariant restore)
    decoder_hmma<<<148, 512, SM_DEC>>>(zcust, zprod, eli, eli + E_LB,
                                       de_W1, de_b1, de_W2, de_b2,
                                       (float*)d_out, E_LB);
}

// round 15
// speedup vs baseline: 1.0302x; 1.0302x over previous
#include <cuda_runtime.h>
#include <cuda_fp16.h>
#include <cstdint>

#define N_PROD 100000
#define N_CUST 50000
#define HID    128
#define DOUT   64
#define E_PP   800000
#define E_PC   800000
#define E_LB   400000

typedef unsigned long long u64;

#define SWZ(x) ((x) ^ (((x) >> 3) & 0x70))
#define TRIGGER_DEPENDENTS() asm volatile("griddepcontrol.launch_dependents;" ::: "memory")
#define GDC_WAIT() asm volatile("griddepcontrol.wait;" ::: "memory")

__device__ __forceinline__ uint32_t smem_u32(const void* p) {
    uint32_t a;
    asm("{ .reg .u64 t; cvta.to.shared.u64 t, %1; cvt.u32.u64 %0, t; }" : "=r"(a) : "l"(p));
    return a;
}
__device__ __forceinline__ void cp16(uint32_t dst, const void* src, int sz) {
    asm volatile("cp.async.cg.shared.global [%0],[%1],16,%2;"
                 :: "r"(dst), "l"(src), "r"(sz));
}
#define CP_COMMIT() asm volatile("cp.async.commit_group;" ::: "memory")
#define CP_WAIT1()  asm volatile("cp.async.wait_group 1;" ::: "memory")
#define CP_WAIT0()  asm volatile("cp.async.wait_group 0;" ::: "memory")

__device__ __forceinline__ void ldm4(uint32_t addr, uint32_t* r) {
    asm volatile("ldmatrix.sync.aligned.m8n8.x4.shared.b16 {%0,%1,%2,%3},[%4];"
                 : "=r"(r[0]), "=r"(r[1]), "=r"(r[2]), "=r"(r[3]) : "r"(addr));
}
__device__ __forceinline__ void mma_f16(float* d, const uint32_t* a,
                                        uint32_t b0, uint32_t b1) {
    asm volatile(
        "mma.sync.aligned.m16n8k16.row.col.f32.f16.f16.f32 "
        "{%0,%1,%2,%3},{%4,%5,%6,%7},{%8,%9},{%0,%1,%2,%3};"
        : "+f"(d[0]), "+f"(d[1]), "+f"(d[2]), "+f"(d[3])
        : "r"(a[0]), "r"(a[1]), "r"(a[2]), "r"(a[3]), "r"(b0), "r"(b1));
}
__device__ __forceinline__ void split1h(float w, unsigned short& h, unsigned short& l) {
    __half hh = __float2half_rn(w);
    __half hl = __float2half_rn(w - __half2float(hh));
    h = __half_as_ushort(hh);
    l = __half_as_ushort(hl);
}
__device__ __forceinline__ u64 pack4h(float a0, float a1, float a2, float a3) {
    __half2 p0 = __floats2half2_rn(a0, a1);
    __half2 p1 = __floats2half2_rn(a2, a3);
    u64 r;
    asm("mov.b64 %0,{%1,%2};" : "=l"(r)
        : "r"(*reinterpret_cast<uint32_t*>(&p0)), "r"(*reinterpret_cast<uint32_t*>(&p1)));
    return r;
}

// ---------------------------------------------------------------------------
// Scratch
// ---------------------------------------------------------------------------
__device__ __half g_xP[(size_t)N_PROD * HID];
__device__ __half g_xC[(size_t)N_CUST * HID];
__device__ __half g_M0[(size_t)N_PROD * HID];
__device__ __half g_M0C[(size_t)N_CUST * HID];
__device__ __half g_P1[(size_t)N_PROD * HID];
__device__ __half g_P2[(size_t)N_PROD * HID];
__device__ __half g_C1[(size_t)N_CUST * HID];
__device__ __half g_zprod[(size_t)N_PROD * DOUT];
__device__ __half g_zcust[(size_t)N_CUST * DOUT];

__device__ int g_cntP[N_PROD];
__device__ int g_cntC[N_CUST];
__device__ int g_offP[N_PROD];
__device__ int g_csrP[E_PP];
__device__ int g_offC[N_CUST];
__device__ int g_csrC[E_PC];
__device__ int g_rankP[E_PP];
__device__ int g_rankC[E_PC];
__device__ u64 g_lbP[128];
__device__ u64 g_lbC[64];

// ---------------------------------------------------------------------------
// Launch 0: convert x -> fp16 planes (independent of CSR chain)
// ---------------------------------------------------------------------------
__global__ void k_convert(const float* __restrict__ xp, const float* __restrict__ xc) {
    if (blockIdx.x == 0 && threadIdx.x == 0) TRIGGER_DEPENDENTS();
    const int NP4 = N_PROD * HID / 4;
    const int NC4 = N_CUST * HID / 4;
    int i = blockIdx.x * blockDim.x + threadIdx.x;
    if (i >= NP4 + NC4) return;
    const float* src; __half* dh; int o;
    if (i < NP4) { src = xp; dh = g_xP; o = i; }
    else { src = xc; dh = g_xC; o = i - NP4; }
    float4 v = *reinterpret_cast<const float4*>(src + (size_t)o * 4);
    *reinterpret_cast<u64*>(dh + (size_t)o * 4) = pack4h(v.x, v.y, v.z, v.w);
}

// Launch 1 [PDL]: count both edge histograms, recording each edge's rank
__global__ void k_count2x(const int* __restrict__ dstP, const int* __restrict__ dstC) {
    int j = blockIdx.x * blockDim.x + threadIdx.x;
    if (j < E_PP) { g_rankP[j] = atomicAdd(&g_cntP[dstP[j]], 1); return; }
    j -= E_PP;
    if (j < E_PC) g_rankC[j] = atomicAdd(&g_cntC[dstC[j]], 1);
}

// ---------------------------------------------------------------------------
// Launch 2 [PDL+wait]: decoupled-lookback scan (P and C segments)
// ---------------------------------------------------------------------------
__device__ void scan_seg(const int* __restrict__ cnt, int n,
                         int* __restrict__ off, u64* __restrict__ st, int bid) {
    __shared__ int s[1024];
    __shared__ int s_prefix;
    int tx = threadIdx.x;
    int gid = bid * 1024 + tx;
    int v = (gid < n) ? cnt[gid] : 0;
    s[tx] = v;
    __syncthreads();
#pragma unroll
    for (int d = 1; d < 1024; d <<= 1) {
        int t = (tx >= d) ? s[tx - d] : 0;
        __syncthreads();
        s[tx] += t;
        __syncthreads();
    }
    int incl = s[tx];
    int total = s[1023];
    if (tx == 0) {
        if (bid == 0) {
            s_prefix = 0;
            atomicExch(st, ((u64)(unsigned)total << 32) | 2ULL);
        } else {
            atomicExch(st + bid, ((u64)(unsigned)total << 32) | 1ULL);
            int run = 0, j = bid - 1;
            while (true) {
                u64 x;
                do { x = atomicAdd(st + j, 0ULL); } while ((x & 3ULL) == 0ULL);
                run += (int)(unsigned)(x >> 32);
                if ((x & 3ULL) == 2ULL) break;
                j--;
            }
            s_prefix = run;
            atomicExch(st + bid, ((u64)(unsigned)(run + total) << 32) | 2ULL);
        }
    }
    __syncthreads();
    if (gid < n) off[gid] = s_prefix + incl - v;
}

__global__ void k_scan2x() {
    GDC_WAIT();
    const int nbP = (N_PROD + 1023) / 1024;
    if ((int)blockIdx.x < nbP)
        scan_seg(g_cntP, N_PROD, g_offP, g_lbP, blockIdx.x);
    else
        scan_seg(g_cntC, N_CUST, g_offC, g_lbC, blockIdx.x - nbP);
}

// Launch 3 [PDL+wait]: atomic-free fill using recorded ranks
__global__ void k_fill2x(const int* __restrict__ eP, const int* __restrict__ eC) {
    GDC_WAIT();
    int e = blockIdx.x * blockDim.x + threadIdx.x;
    if (e < E_PP) {
        int d = eP[E_PP + e];
        g_csrP[g_offP[d] + g_rankP[e]] = eP[e];
    } else if (e < E_PP + E_PC) {
        int j = e - E_PP;
        int d = eC[E_PC + j];
        g_csrC[g_offC[d] + g_rankC[j]] = eC[j];
    }
}

// ---------------------------------------------------------------------------
// Mean aggregation body (R13 best: HADD2 pairwise tree, warp-per-row)
// ---------------------------------------------------------------------------
__device__ __forceinline__ void agg_body(const __half* __restrict__ x,
                                         const int* __restrict__ off,
                                         const int* __restrict__ csr,
                                         __half* __restrict__ o,
                                         int w, int n, int E, int lane) {
    int beg = off[w];
    int end = (w + 1 < n) ? off[w + 1] : E;
    float a0 = 0.f, a1 = 0.f, a2 = 0.f, a3 = 0.f;
    int j = beg;
    for (; j + 3 < end; j += 4) {
        int s0 = csr[j], s1 = csr[j + 1], s2 = csr[j + 2], s3 = csr[j + 3];
        u64 p0 = __ldg(reinterpret_cast<const u64*>(x + (size_t)s0 * HID + lane * 4));
        u64 p1 = __ldg(reinterpret_cast<const u64*>(x + (size_t)s1 * HID + lane * 4));
        u64 p2 = __ldg(reinterpret_cast<const u64*>(x + (size_t)s2 * HID + lane * 4));
        u64 p3 = __ldg(reinterpret_cast<const u64*>(x + (size_t)s3 * HID + lane * 4));
        uint2 u0 = *reinterpret_cast<uint2*>(&p0);
        uint2 u1 = *reinterpret_cast<uint2*>(&p1);
        uint2 u2 = *reinterpret_cast<uint2*>(&p2);
        uint2 u3 = *reinterpret_cast<uint2*>(&p3);
        __half2 q0 = __hadd2(*reinterpret_cast<__half2*>(&u0.x),
                             *reinterpret_cast<__half2*>(&u1.x));
        __half2 q1 = __hadd2(*reinterpret_cast<__half2*>(&u0.y),
                             *reinterpret_cast<__half2*>(&u1.y));
        __half2 q2 = __hadd2(*reinterpret_cast<__half2*>(&u2.x),
                             *reinterpret_cast<__half2*>(&u3.x));
        __half2 q3 = __hadd2(*reinterpret_cast<__half2*>(&u2.y),
                             *reinterpret_cast<__half2*>(&u3.y));
        float2 f;
        f = __half22float2(q0); a0 += f.x; a1 += f.y;
        f = __half22float2(q1); a2 += f.x; a3 += f.y;
        f = __half22float2(q2); a0 += f.x; a1 += f.y;
        f = __half22float2(q3); a2 += f.x; a3 += f.y;
    }
    for (; j < end; j++) {
        int s0 = csr[j];
        u64 p = __ldg(reinterpret_cast<const u64*>(x + (size_t)s0 * HID + lane * 4));
        uint2 uu = *reinterpret_cast<uint2*>(&p);
        float2 f0 = __half22float2(*reinterpret_cast<__half2*>(&uu.x));
        float2 f1 = __half22float2(*reinterpret_cast<__half2*>(&uu.y));
        a0 += f0.x; a1 += f0.y; a2 += f1.x; a3 += f1.y;
    }
    float sc = (end > beg) ? 1.0f / (float)(end - beg) : 0.f;
    *reinterpret_cast<u64*>(o + (size_t)w * HID + lane * 4) =
        pack4h(a0 * sc, a1 * sc, a2 * sc, a3 * sc);
}

// Both x-aggregations in one launch
__global__ void agg2x() {
    int w = (blockIdx.x * blockDim.x + threadIdx.x) >> 5;
    int lane = threadIdx.x & 31;
    if (w < N_PROD)
        agg_body(g_xP, g_offP, g_csrP, g_M0, w, N_PROD, E_PP, lane);
    else if (w < N_PROD + N_CUST)
        agg_body(g_xP, g_offC, g_csrC, g_M0C, w - N_PROD, N_CUST, E_PC, lane);
}

// Both layer-2 aggregations in one launch
__global__ void agg2b() {
    int w = (blockIdx.x * blockDim.x + threadIdx.x) >> 5;
    int lane = threadIdx.x & 31;
    if (w < N_PROD)
        agg_body(g_P1, g_offP, g_csrP, g_M0, w, N_PROD, E_PP, lane);
    else if (w < N_PROD + N_CUST)
        agg_body(g_P2, g_offC, g_csrC, g_M0C, w - N_PROD, N_CUST, E_PC, lane);
}

// ---------------------------------------------------------------------------
// Dual f16 GEMM (2-term weight split), K=256, N=128, MTILE=256, relu.
//   FUSE2: restage relu'd tile and run second GEMM (128->64), write fp16 z.
// ---------------------------------------------------------------------------
template <bool FUSE2>
__global__ __launch_bounds__(512, 1) void hmma_dual(
    const __half* __restrict__ A, const __half* __restrict__ X,
    const float* __restrict__ Wl, const float* __restrict__ Wr,
    const float* __restrict__ bias,
    const float* __restrict__ W2, const float* __restrict__ b2,
    __half* __restrict__ outP, __half* __restrict__ out2,
    int n, int trig)
{
    if (trig) TRIGGER_DEPENDENTS();
    constexpr int KSTEPS = 16;
    constexpr int NF2    = 8;
    constexpr int MTILE  = 256;
    constexpr int CHUNKB = MTILE * 128;
    constexpr int BOFF   = 1024 + 2 * CHUNKB;
    constexpr int BSPLIT = KSTEPS * NF2 * 32 * 16;
    constexpr int BOFF2  = BOFF + 2 * BSPLIT;
    constexpr int BSPLIT2 = 8 * 4 * 32 * 16;
    constexpr int NCHUNK = 4;
    constexpr int CPOPS  = MTILE * 8;

    extern __shared__ char smem[];
    const uint32_t sb = smem_u32(smem);
    const int tid = threadIdx.x;
    const int w = tid >> 5, lane = tid & 31;
    const int g     = w & 1;
    const int warpM = (w >> 1) * 32;

    float* bs = (float*)smem;
    float* bs2 = (float*)(smem + 512);
    if (tid < 128) bs[tid] = bias[tid];
    if (FUSE2 && tid >= 128 && tid < 192) bs2[tid - 128] = b2[tid - 128];

    for (int idx = tid; idx < 2 * KSTEPS * NF2 * 32; idx += 512) {
        int l = idx & 31;
        int rest = idx >> 5;
        int nfp = rest % NF2;
        int rest2 = rest / NF2;
        int ks = rest2 % KSTEPS;
        int s = rest2 / KSTEPS;
        uint32_t vals[4];
#pragma unroll
        for (int e = 0; e < 2; e++) {
            int nf = nfp * 2 + e;
            int nn = nf * 8 + (l >> 2);
            int k0 = ks * 16 + (l & 3) * 2;
            const float* wp = Wl;
            int kk = k0;
            if (k0 >= 128) { wp = Wr; kk = k0 - 128; }
            float2 wa = *reinterpret_cast<const float2*>(wp + nn * 128 + kk);
            float2 wb = *reinterpret_cast<const float2*>(wp + nn * 128 + kk + 8);
            unsigned short h, lo, r00, r01, r10, r11;
            split1h(wa.x, h, lo); r00 = s ? lo : h;
            split1h(wa.y, h, lo); r01 = s ? lo : h;
            split1h(wb.x, h, lo); r10 = s ? lo : h;
            split1h(wb.y, h, lo); r11 = s ? lo : h;
            vals[e * 2 + 0] = (uint32_t)r00 | ((uint32_t)r01 << 16);
            vals[e * 2 + 1] = (uint32_t)r10 | ((uint32_t)r11 << 16);
        }
        *reinterpret_cast<uint4*>(smem + BOFF + (size_t)idx * 16) =
            make_uint4(vals[0], vals[1], vals[2], vals[3]);
    }
    if (FUSE2) {
        for (int idx = tid; idx < 2 * 8 * 4 * 32; idx += 512) {
            int l = idx & 31;
            int rest = idx >> 5;
            int nfp = rest % 4;
            int rest2 = rest / 4;
            int ks = rest2 % 8;
            int s = rest2 / 8;
            uint32_t vals[4];
#pragma unroll
            for (int e = 0; e < 2; e++) {
                int nf = nfp * 2 + e;
                int nn = nf * 8 + (l >> 2);
                int k0 = ks * 16 + (l & 3) * 2;
                float2 wa = *reinterpret_cast<const float2*>(W2 + nn * 128 + k0);
                float2 wb = *reinterpret_cast<const float2*>(W2 + nn * 128 + k0 + 8);
                unsigned short h, lo, r00, r01, r10, r11;
                split1h(wa.x, h, lo); r00 = s ? lo : h;
                split1h(wa.y, h, lo); r01 = s ? lo : h;
                split1h(wb.x, h, lo); r10 = s ? lo : h;
                split1h(wb.y, h, lo); r11 = s ? lo : h;
                vals[e * 2 + 0] = (uint32_t)r00 | ((uint32_t)r01 << 16);
                vals[e * 2 + 1] = (uint32_t)r10 | ((uint32_t)r11 << 16);
            }
            *reinterpret_cast<uint4*>(smem + BOFF2 + (size_t)idx * 16) =
                make_uint4(vals[0], vals[1], vals[2], vals[3]);
        }
    }
    __syncthreads();

    const int ntiles = (n + MTILE - 1) / MTILE;

    for (int tt = blockIdx.x; tt < ntiles; tt += gridDim.x) {
        float acc[2][8][4];
#pragma unroll
        for (int t = 0; t < 2; t++)
#pragma unroll
            for (int nf = 0; nf < 8; nf++)
#pragma unroll
                for (int q = 0; q < 4; q++) acc[t][nf][q] = 0.f;

        auto stage = [&](int c, int b) {
            const __half* src = (c >= 2) ? X : A;
            const int colbase = (c & 1) * 64;
#pragma unroll
            for (int it = 0; it < CPOPS / 512; it++) {
                int u = tid + it * 512;
                int r0 = u >> 3;
                int ch = u & 7;
                int gr = tt * MTILE + r0;
                uint32_t dst = sb + 1024 + b * CHUNKB +
                               SWZ((uint32_t)(r0 * 128 + ch * 16));
                const void* gp = src + (size_t)gr * 128 + colbase + ch * 8;
                cp16(dst, gp, (gr < n) ? 16 : 0);
            }
            CP_COMMIT();
        };

        stage(0, 0);

        for (int c = 0; c < NCHUNK; c++) {
            if (c + 1 < NCHUNK) { stage(c + 1, (c + 1) & 1); CP_WAIT1(); }
            else CP_WAIT0();
            __syncthreads();

            const uint32_t abase = sb + 1024 + (c & 1) * CHUNKB;
#pragma unroll
            for (int ksl = 0; ksl < 4; ksl++) {
                const int ks = c * 4 + ksl;
                uint32_t ah[2][4];
#pragma unroll
                for (int t = 0; t < 2; t++) {
                    int arow = warpM + t * 16 + (lane & 15);
                    int colb = ksl * 32 + ((lane >> 4) << 4);
                    ldm4(abase + SWZ((uint32_t)(arow * 128 + colb)), ah[t]);
                }
                uint4 Bq[4];
                {
                    size_t base = (size_t)BOFF +
                        ((size_t)(ks * NF2 + g * 4) * 32 + lane) * 16;
#pragma unroll
                    for (int p = 0; p < 4; p++)
                        Bq[p] = *reinterpret_cast<const uint4*>(smem + base + p * 512);
                }
#pragma unroll
                for (int t = 0; t < 2; t++)
#pragma unroll
                    for (int nf = 0; nf < 8; nf++) {
                        uint32_t b0 = (nf & 1) ? Bq[nf >> 1].z : Bq[nf >> 1].x;
                        uint32_t b1 = (nf & 1) ? Bq[nf >> 1].w : Bq[nf >> 1].y;
                        mma_f16(acc[t][nf], ah[t], b0, b1);
                    }
                {
                    size_t base = (size_t)BOFF + BSPLIT +
                        ((size_t)(ks * NF2 + g * 4) * 32 + lane) * 16;
#pragma unroll
                    for (int p = 0; p < 4; p++)
                        Bq[p] = *reinterpret_cast<const uint4*>(smem + base + p * 512);
                }
#pragma unroll
                for (int t = 0; t < 2; t++)
#pragma unroll
                    for (int nf = 0; nf < 8; nf++) {
                        uint32_t b0 = (nf & 1) ? Bq[nf >> 1].z : Bq[nf >> 1].x;
                        uint32_t b1 = (nf & 1) ? Bq[nf >> 1].w : Bq[nf >> 1].y;
                        mma_f16(acc[t][nf], ah[t], b0, b1);
                    }
            }
            __syncthreads();
        }

        if (!FUSE2) {
#pragma unroll
            for (int t = 0; t < 2; t++) {
                int rbase = tt * MTILE + warpM + t * 16 + (lane >> 2);
#pragma unroll
                for (int nf = 0; nf < 8; nf++) {
                    int col = g * 64 + nf * 8 + (lane & 3) * 2;
#pragma unroll
                    for (int hh = 0; hh < 2; hh++) {
                        int row = rbase + hh * 8;
                        if (row < n) {
                            float ox = fmaxf(acc[t][nf][hh * 2 + 0] + bs[col], 0.f);
                            float oy = fmaxf(acc[t][nf][hh * 2 + 1] + bs[col + 1], 0.f);
                            __half2 hp = __floats2half2_rn(ox, oy);
                            *reinterpret_cast<uint32_t*>(outP + (size_t)row * 128 + col) =
                                *reinterpret_cast<uint32_t*>(&hp);
                        }
                    }
                }
            }
        } else {
#pragma unroll
            for (int t = 0; t < 2; t++) {
                int rl = warpM + t * 16 + (lane >> 2);
#pragma unroll
                for (int nf = 0; nf < 8; nf++) {
                    int col = g * 64 + nf * 8 + (lane & 3) * 2;
#pragma unroll
                    for (int hh = 0; hh < 2; hh++) {
                        int r = rl + hh * 8;
                        float ox = fmaxf(acc[t][nf][hh * 2 + 0] + bs[col], 0.f);
                        float oy = fmaxf(acc[t][nf][hh * 2 + 1] + bs[col + 1], 0.f);
                        __half2 hp = __floats2half2_rn(ox, oy);
                        uint32_t off = SWZ((uint32_t)(r * 128 + (col & 63) * 2));
                        *reinterpret_cast<uint32_t*>(smem + 1024 + g * CHUNKB + off) =
                            *reinterpret_cast<uint32_t*>(&hp);
                    }
                }
            }
            __syncthreads();

            float acc2[2][4][4];
#pragma unroll
            for (int t = 0; t < 2; t++)
#pragma unroll
                for (int nf = 0; nf < 4; nf++)
#pragma unroll
                    for (int q = 0; q < 4; q++) acc2[t][nf][q] = 0.f;

#pragma unroll
            for (int ks2 = 0; ks2 < 8; ks2++) {
                const int chunk = ks2 >> 2, ksl2 = ks2 & 3;
                const uint32_t abase2 = sb + 1024 + chunk * CHUNKB;
                uint32_t ah2[2][4];
#pragma unroll
                for (int t = 0; t < 2; t++) {
                    int arow = warpM + t * 16 + (lane & 15);
                    int colb = ksl2 * 32 + ((lane >> 4) << 4);
                    ldm4(abase2 + SWZ((uint32_t)(arow * 128 + colb)), ah2[t]);
                }
                uint4 Bq[2];
                {
                    size_t base = (size_t)BOFF2 +
                        ((size_t)(ks2 * 4 + g * 2) * 32 + lane) * 16;
                    Bq[0] = *reinterpret_cast<const uint4*>(smem + base);
                    Bq[1] = *reinterpret_cast<const uint4*>(smem + base + 512);
                }
#pragma unroll
                for (int t = 0; t < 2; t++)
#pragma unroll
                    for (int nf = 0; nf < 4; nf++) {
                        uint32_t b0 = (nf & 1) ? Bq[nf >> 1].z : Bq[nf >> 1].x;
                        uint32_t b1 = (nf & 1) ? Bq[nf >> 1].w : Bq[nf >> 1].y;
                        mma_f16(acc2[t][nf], ah2[t], b0, b1);
                    }
                {
                    size_t base = (size_t)BOFF2 + BSPLIT2 +
                        ((size_t)(ks2 * 4 + g * 2) * 32 + lane) * 16;
                    Bq[0] = *reinterpret_cast<const uint4*>(smem + base);
                    Bq[1] = *reinterpret_cast<const uint4*>(smem + base + 512);
                }
#pragma unroll
                for (int t = 0; t < 2; t++)
#pragma unroll
                    for (int nf = 0; nf < 4; nf++) {
                        uint32_t b0 = (nf & 1) ? Bq[nf >> 1].z : Bq[nf >> 1].x;
                        uint32_t b1 = (nf & 1) ? Bq[nf >> 1].w : Bq[nf >> 1].y;
                        mma_f16(acc2[t][nf], ah2[t], b0, b1);
                    }
            }

#pragma unroll
            for (int t = 0; t < 2; t++) {
                int rbase = tt * MTILE + warpM + t * 16 + (lane >> 2);
#pragma unroll
                for (int nf = 0; nf < 4; nf++) {
                    int col = g * 32 + nf * 8 + (lane & 3) * 2;
#pragma unroll
                    for (int hh = 0; hh < 2; hh++) {
                        int row = rbase + hh * 8;
                        if (row < n) {
                            __half2 hp = __floats2half2_rn(
                                acc2[t][nf][hh * 2 + 0] + bs2[col],
                                acc2[t][nf][hh * 2 + 1] + bs2[col + 1]);
                            *reinterpret_cast<uint32_t*>(out2 + (size_t)row * 64 + col) =
                                *reinterpret_cast<uint32_t*>(&hp);
                        }
                    }
                }
            }
            __syncthreads();
        }
    }
}

// ---------------------------------------------------------------------------
// HMMA decoder (+ scratch zeroing prologue)
// ---------------------------------------------------------------------------
__global__ __launch_bounds__(512, 1) void decoder_hmma(
    const __half* __restrict__ zc, const __half* __restrict__ zp,
    const int* __restrict__ rowIdx, const int* __restrict__ colIdx,
    const float* __restrict__ W1, const float* __restrict__ b1,
    const float* __restrict__ w2, const float* __restrict__ b2,
    float* __restrict__ out, int nE)
{
    constexpr int MTILE  = 256;
    constexpr int CHUNKB = MTILE * 128;
    constexpr int BOFF   = 1024 + 2 * CHUNKB;
    constexpr int BSPLIT = 8 * 4 * 32 * 16;

    for (int i = blockIdx.x * blockDim.x + threadIdx.x; i < N_PROD;
         i += gridDim.x * blockDim.x) {
        g_cntP[i] = 0;
        if (i < N_CUST) g_cntC[i] = 0;
        if (i < 128) g_lbP[i] = 0;
        if (i < 64) g_lbC[i] = 0;
    }

    extern __shared__ char smem[];
    const uint32_t sb = smem_u32(smem);
    const int tid = threadIdx.x;
    const int w = tid >> 5, lane = tid & 31;
    const int warpM = w * 16;

    float* ps = (float*)smem;
    if (tid < 64) ps[tid] = b1[tid];
    else if (tid < 128) ps[tid] = w2[tid - 64];
    else if (tid == 128) ps[128] = b2[0];

    for (int idx = tid; idx < 2 * 8 * 4 * 32; idx += 512) {
        int l = idx & 31;
        int rest = idx >> 5;
        int nfp = rest % 4;
        int rest2 = rest / 4;
        int ks = rest2 % 8;
        int s = rest2 / 8;
        uint32_t vals[4];
#pragma unroll
        for (int e = 0; e < 2; e++) {
            int nf = nfp * 2 + e;
            int nn = nf * 8 + (l >> 2);
            int k0 = ks * 16 + (l & 3) * 2;
            float2 wa = *reinterpret_cast<const float2*>(W1 + nn * 128 + k0);
            float2 wb = *reinterpret_cast<const float2*>(W1 + nn * 128 + k0 + 8);
            unsigned short h, lo, r00, r01, r10, r11;
            split1h(wa.x, h, lo); r00 = s ? lo : h;
            split1h(wa.y, h, lo); r01 = s ? lo : h;
            split1h(wb.x, h, lo); r10 = s ? lo : h;
            split1h(wb.y, h, lo); r11 = s ? lo : h;
            vals[e * 2 + 0] = (uint32_t)r00 | ((uint32_t)r01 << 16);
            vals[e * 2 + 1] = (uint32_t)r10 | ((uint32_t)r11 << 16);
        }
        *reinterpret_cast<uint4*>(smem + BOFF + (size_t)idx * 16) =
            make_uint4(vals[0], vals[1], vals[2], vals[3]);
    }
    __syncthreads();

    const int ntiles = (nE + MTILE - 1) / MTILE;

    for (int tt = blockIdx.x; tt < ntiles; tt += gridDim.x) {
        float acc[8][4];
#pragma unroll
        for (int nf = 0; nf < 8; nf++)
#pragma unroll
            for (int q = 0; q < 4; q++) acc[nf][q] = 0.f;

        auto stage = [&](int c, int b) {
            const __half* src = (c == 0) ? zc : zp;
            const int* idxp = (c == 0) ? rowIdx : colIdx;
#pragma unroll
            for (int it = 0; it < 4; it++) {
                int u = tid + it * 512;
                int r0 = u >> 3;
                int ch = u & 7;
                int e = tt * MTILE + r0;
                int idx = (e < nE) ? __ldg(idxp + e) : -1;
                uint32_t dst = sb + 1024 + b * CHUNKB +
                               SWZ((uint32_t)(r0 * 128 + ch * 16));
                const void* gp = src + (size_t)(idx < 0 ? 0 : idx) * 64 + ch * 8;
                cp16(dst, gp, (idx >= 0) ? 16 : 0);
            }
            CP_COMMIT();
        };

        stage(0, 0);

        for (int c = 0; c < 2; c++) {
            if (c == 0) { stage(1, 1); CP_WAIT1(); }
            else CP_WAIT0();
            __syncthreads();

            const uint32_t abase = sb + 1024 + c * CHUNKB;
#pragma unroll
            for (int ksl = 0; ksl < 4; ksl++) {
                const int ks = c * 4 + ksl;
                uint32_t ah[4];
                {
                    int arow = warpM + (lane & 15);
                    int colb = ksl * 32 + ((lane >> 4) << 4);
                    ldm4(abase + SWZ((uint32_t)(arow * 128 + colb)), ah);
                }
                uint4 Bq[4];
                {
                    size_t base = (size_t)BOFF + ((size_t)(ks * 4) * 32 + lane) * 16;
#pragma unroll
                    for (int p = 0; p < 4; p++)
                        Bq[p] = *reinterpret_cast<const uint4*>(smem + base + p * 512);
                }
#pragma unroll
                for (int nf = 0; nf < 8; nf++) {
                    uint32_t b0 = (nf & 1) ? Bq[nf >> 1].z : Bq[nf >> 1].x;
                    uint32_t b1v = (nf & 1) ? Bq[nf >> 1].w : Bq[nf >> 1].y;
                    mma_f16(acc[nf], ah, b0, b1v);
                }
                {
                    size_t base = (size_t)BOFF + BSPLIT + ((size_t)(ks * 4) * 32 + lane) * 16;
#pragma unroll
                    for (int p = 0; p < 4; p++)
                        Bq[p] = *reinterpret_cast<const uint4*>(smem + base + p * 512);
                }
#pragma unroll
                for (int nf = 0; nf < 8; nf++) {
                    uint32_t b0 = (nf & 1) ? Bq[nf >> 1].z : Bq[nf >> 1].x;
                    uint32_t b1v = (nf & 1) ? Bq[nf >> 1].w : Bq[nf >> 1].y;
                    mma_f16(acc[nf], ah, b0, b1v);
                }
            }
            __syncthreads();
        }

        {
            float p0 = 0.f, p1 = 0.f;
#pragma unroll
            for (int nf = 0; nf < 8; nf++) {
                int col = nf * 8 + (lane & 3) * 2;
                float w20 = ps[64 + col], w21 = ps[64 + col + 1];
                float bb0 = ps[col], bb1 = ps[col + 1];
                p0 += fmaxf(acc[nf][0] + bb0, 0.f) * w20 +
                      fmaxf(acc[nf][1] + bb1, 0.f) * w21;
                p1 += fmaxf(acc[nf][2] + bb0, 0.f) * w20 +
                      fmaxf(acc[nf][3] + bb1, 0.f) * w21;
            }
            p0 += __shfl_xor_sync(0xffffffff, p0, 1);
            p0 += __shfl_xor_sync(0xffffffff, p0, 2);
            p1 += __shfl_xor_sync(0xffffffff, p1, 1);
            p1 += __shfl_xor_sync(0xffffffff, p1, 2);
            if ((lane & 3) == 0) {
                int e0 = tt * MTILE + warpM + (lane >> 2);
                if (e0 < nE) out[e0] = p0 + ps[128];
                if (e0 + 8 < nE) out[e0 + 8] = p1 + ps[128];
            }
        }
    }
}

// ---------------------------------------------------------------------------
// Host orchestration
// ---------------------------------------------------------------------------
extern "C" void kernel_launch(void* const* d_in, const int* in_sizes, int n_in,
                              void* d_out, int out_size) {
    const float* x_prod = (const float*)d_in[0];
    const float* x_cust = (const float*)d_in[1];
    const int* pp = (const int*)d_in[2];
    const int* pc = (const int*)d_in[3];
    const int* eli = (const int*)d_in[4];

    bool sig = (in_sizes[6] == HID);
    const float* it_W1l = (const float*)d_in[5];
    const float* it_W1r = (const float*)d_in[sig ? 7 : 6];
    const float* it_b1  = (const float*)d_in[sig ? 6 : 7];
    const float* it_W2l = (const float*)d_in[8];
    const float* it_W2r = (const float*)d_in[sig ? 10 : 9];
    const float* it_b2  = (const float*)d_in[sig ? 9 : 10];
    const float* it_Wlin = (const float*)d_in[11];
    const float* it_blin = (const float*)d_in[12];
    const float* us_W1l = (const float*)d_in[13];
    const float* us_W1r = (const float*)d_in[sig ? 15 : 14];
    const float* us_b1  = (const float*)d_in[sig ? 14 : 15];
    const float* us_W2l = (const float*)d_in[16];
    const float* us_W2r = (const float*)d_in[sig ? 18 : 17];
    const float* us_b2  = (const float*)d_in[sig ? 17 : 18];
    const float* us_W3l = (const float*)d_in[19];
    const float* us_W3r = (const float*)d_in[sig ? 21 : 20];
    const float* us_b3  = (const float*)d_in[sig ? 20 : 21];
    const float* us_Wlin = (const float*)d_in[22];
    const float* us_blin = (const float*)d_in[23];
    const float* de_W1 = (const float*)d_in[24];
    const float* de_b1 = (const float*)d_in[25];
    const float* de_W2 = (const float*)d_in[26];
    const float* de_b2 = (const float*)d_in[27];

#define GETP(var, sym, T) T* var; cudaGetSymbolAddress((void**)&var, sym)
    GETP(xP, g_xP, __half); GETP(xC, g_xC, __half);
    GETP(M0, g_M0, __half); GETP(M0C, g_M0C, __half);
    GETP(P1, g_P1, __half); GETP(P2, g_P2, __half);
    GETP(C1, g_C1, __half);
    GETP(zprod, g_zprod, __half); GETP(zcust, g_zcust, __half);
    GETP(offP, g_offP, int); GETP(csrP, g_csrP, int);
    GETP(offC, g_offC, int); GETP(csrC, g_csrC, int);
#undef GETP

    constexpr int SM_PLAIN = 1024 + 2 * 32768 + 2 * 65536;   // 197632
    constexpr int SM_FUSED = SM_PLAIN + 2 * 16384;           // 230400
    constexpr int SM_DEC   = 1024 + 2 * 32768 + 2 * 16384;   // 99328
    cudaFuncSetAttribute((hmma_dual<false>),
                         cudaFuncAttributeMaxDynamicSharedMemorySize, SM_PLAIN);
    cudaFuncSetAttribute((hmma_dual<true>),
                         cudaFuncAttributeMaxDynamicSharedMemorySize, SM_FUSED);
    cudaFuncSetAttribute(decoder_hmma,
                         cudaFuncAttributeMaxDynamicSharedMemorySize, SM_DEC);

    const int nbP = (N_PROD + 1023) / 1024;
    const int nbC = (N_CUST + 1023) / 1024;
    const int CVT_ITEMS = (N_PROD + N_CUST) * HID / 4;
    const int agg2x_grid = ((N_PROD + N_CUST) * 32 + 255) / 256;

    cudaLaunchAttribute pdlAttr[1];
    pdlAttr[0].id = cudaLaunchAttributeProgrammaticStreamSerialization;
    pdlAttr[0].val.programmaticStreamSerializationAllowed = 1;

    auto mkCfg = [&](int grid, int block, int smem) {
        cudaLaunchConfig_t c{};
        c.gridDim = dim3(grid); c.blockDim = dim3(block);
        c.dynamicSmemBytes = smem; c.stream = 0;
        c.attrs = pdlAttr; c.numAttrs = 1;
        return c;
    };

    // 0: convert (triggers immediately so CSR chain overlaps)
    k_convert<<<(CVT_ITEMS + 255) / 256, 256>>>(x_prod, x_cust);
    // 1: counts + ranks [PDL]
    {
        cudaLaunchConfig_t c = mkCfg((E_PP + E_PC + 255) / 256, 256, 0);
        cudaLaunchKernelEx(&c, k_count2x, (const int*)(pp + E_PP), (const int*)(pc + E_PC));
    }
    // 2: scan [PDL + gdc.wait]
    {
        cudaLaunchConfig_t c = mkCfg(nbP + nbC, 1024, 0);
        cudaLaunchKernelEx(&c, k_scan2x);
    }
    // 3: atomic-free fill [PDL + gdc.wait]
    {
        cudaLaunchConfig_t c = mkCfg((E_PP + E_PC + 255) / 256, 256, 0);
        cudaLaunchKernelEx(&c, k_fill2x, (const int*)pp, (const int*)pc);
    }

    // 4: both x-aggregations
    agg2x<<<agg2x_grid, 256>>>();

    // 5-7: G1, G2, G5 mutually independent
    hmma_dual<false><<<148, 512, SM_PLAIN>>>(
        M0, xP, it_W1l, it_W1r, it_b1, nullptr, nullptr, P1, nullptr, N_PROD, 1);
    {
        cudaLaunchConfig_t c = mkCfg(148, 512, SM_PLAIN);
        cudaLaunchKernelEx(&c, hmma_dual<false>,
            (const __half*)M0, (const __half*)xP, us_W1l, us_W1r, us_b1,
            (const float*)nullptr, (const float*)nullptr,
            (__half*)P2, (__half*)nullptr, (int)N_PROD, 1);
        cudaLaunchKernelEx(&c, hmma_dual<false>,
            (const __half*)M0C, (const __half*)xC, us_W2l, us_W2r, us_b2,
            (const float*)nullptr, (const float*)nullptr,
            (__half*)C1, (__half*)nullptr, (int)N_CUST, 0);
    }

    // 8: merged layer-2 aggregations
    agg2b<<<agg2x_grid, 256>>>();

    // 9-10: fused G3 ‖ fused G6
    hmma_dual<true><<<148, 512, SM_FUSED>>>(
        M0, P1, it_W2l, it_W2r, it_b2, it_Wlin, it_blin, nullptr, zprod, N_PROD, 1);
    {
        cudaLaunchConfig_t c = mkCfg(148, 512, SM_FUSED);
        cudaLaunchKernelEx(&c, hmma_dual<true>,
            (const __half*)M0C, (const __half*)C1, us_W3l, us_W3r, us_b3,
            us_Wlin, us_blin, (__half*)nullptr, (__half*)zcust, (int)N_CUST, 0);
    }

    // 11: HMMA decoder (+ zero-invariant restore)
    decoder_hmma<<<148, 512, SM_DEC>>>(zcust, zprod, eli, eli + E_LB,
                                       de_W1, de_b1, de_W2, de_b2,
                                       (float*)d_out, E_LB);
}